// round 11
// baseline (speedup 1.0000x reference)
#include <cuda_runtime.h>
#include <cuda_fp16.h>
#include <math.h>
#include <stdint.h>

// ---- dims ----
#define BB 2048
#define TT 128
#define VV 25
#define HH 512
#define NC 100
#define KTOT 544          // 512 (h) + 32 (x padded from 25)
#define TM 64
#define TN 64
#define NCH 17            // 544/32

// smem: rows of 32 halves padded to 80B (conflict-free ldmatrix)
#define ROWB 80
#define TILE_BYTES (64 * ROWB)          // 5120
#define STAGE_BYTES (4 * TILE_BYTES)    // Ahi, Alo, Bhi, Blo = 20480
#define SMEM_TOTAL (2 * STAGE_BYTES)    // 40960

// ---- persistent device state ----
__device__ __align__(1024) __half g_W_hi[2048][KTOT];   // permuted: row C=4j+gate, cols k
__device__ __align__(1024) __half g_W_lo[2048][KTOT];
__device__ __align__(1024) __half g_x_hi[TT][BB][32];
__device__ __align__(1024) __half g_x_lo[TT][BB][32];
__device__ __align__(1024) __half g_h_hi[2][BB][HH];
__device__ __align__(1024) __half g_h_lo[2][BB][HH];
__device__ __align__(1024) float  g_c[(size_t)HH * BB]; // [j][row]
__device__ float g_bias[2048];

// ---- helpers ----
__device__ __forceinline__ uint32_t s2u(const void* p) {
    uint32_t a;
    asm("{ .reg .u64 t; cvta.to.shared.u64 t, %1; cvt.u32.u64 %0, t; }" : "=r"(a) : "l"(p));
    return a;
}
__device__ __forceinline__ void ldsm4(uint32_t (&r)[4], uint32_t addr) {
    asm volatile("ldmatrix.sync.aligned.m8n8.x4.shared.b16 {%0,%1,%2,%3}, [%4];"
        : "=r"(r[0]), "=r"(r[1]), "=r"(r[2]), "=r"(r[3]) : "r"(addr));
}
__device__ __forceinline__ void mma16816(float (&d)[4], const uint32_t (&a)[4],
                                         uint32_t b0, uint32_t b1) {
    asm volatile("mma.sync.aligned.m16n8k16.row.col.f32.f16.f16.f32 "
        "{%0,%1,%2,%3}, {%4,%5,%6,%7}, {%8,%9}, {%0,%1,%2,%3};"
        : "+f"(d[0]), "+f"(d[1]), "+f"(d[2]), "+f"(d[3])
        : "r"(a[0]), "r"(a[1]), "r"(a[2]), "r"(a[3]), "r"(b0), "r"(b1));
}
__device__ __forceinline__ void cpasync16(uint32_t dst, const void* src) {
    size_t g = __cvta_generic_to_global(src);
    asm volatile("cp.async.cg.shared.global [%0], [%1], 16;" :: "r"(dst), "l"(g));
}
__device__ __forceinline__ float fsig(float x) { return 1.0f / (1.0f + __expf(-x)); }
__device__ __forceinline__ float ftanh_(float x) {
    float e = __expf(2.0f * x);
    return 1.0f - 2.0f / (e + 1.0f);
}

// ---- prep kernels ----
__global__ void prep_w(const float* __restrict__ W_ih, const float* __restrict__ W_hh,
                       const float* __restrict__ b_ih, const float* __restrict__ b_hh) {
    int idx = blockIdx.x * blockDim.x + threadIdx.x;
    if (idx >= 2048 * KTOT) return;
    int C = idx / KTOT, k = idx - C * KTOT;
    int orig = (C & 3) * HH + (C >> 2);     // gate-major -> interleaved
    float v = 0.0f;
    if (k < HH) v = W_hh[(size_t)orig * HH + k];
    else if (k - HH < VV) v = W_ih[(size_t)orig * VV + (k - HH)];
    __half hi = __float2half(v);
    g_W_hi[C][k] = hi;
    g_W_lo[C][k] = __float2half(v - __half2float(hi));
    if (k == 0) g_bias[C] = b_ih[orig] + b_hh[orig];
}
__global__ void prep_x(const float* __restrict__ msgs) {
    int idx = blockIdx.x * blockDim.x + threadIdx.x;
    if (idx >= TT * BB * 32) return;
    int kk = idx & 31, rt = idx >> 5;
    int row = rt & (BB - 1), t = rt >> 11;
    float v = (kk < VV) ? msgs[((size_t)row * TT + t) * VV + kk] : 0.0f;
    __half hi = __float2half(v);
    g_x_hi[t][row][kk] = hi;
    g_x_lo[t][row][kk] = __float2half(v - __half2float(hi));
}
__global__ void init_state() {
    size_t i = (size_t)blockIdx.x * blockDim.x + threadIdx.x;
    if (i < (size_t)BB * HH) {
        g_h_hi[0][0][i] = __float2half(0.0f);
        g_h_lo[0][0][i] = __float2half(0.0f);
        g_c[i] = 0.0f;
    }
}

// ---- per-chunk producer: 4 tiles x 64 rows x 4x16B chunks / 128 thr = 8 iters ----
__device__ __forceinline__ void produce(uint32_t sb, int stage, int kc, int t,
                                        int row0, int C0, int tid) {
    const int hb = t & 1;
    #pragma unroll
    for (int i = 0; i < 8; i++) {
        int p = tid + i * 128;
        int tile = p >> 8;            // 0..3
        int r = (p >> 2) & 63;
        int cc = p & 3;
        int koff = kc * 32 + cc * 8;  // halves
        uint32_t dst = sb + stage * STAGE_BYTES + tile * TILE_BYTES + r * ROWB + cc * 16;
        const void* src;
        if (tile == 0)
            src = (kc < 16) ? (const void*)&g_h_hi[hb][row0 + r][koff]
                            : (const void*)&g_x_hi[t][row0 + r][koff - 512];
        else if (tile == 1)
            src = (kc < 16) ? (const void*)&g_h_lo[hb][row0 + r][koff]
                            : (const void*)&g_x_lo[t][row0 + r][koff - 512];
        else if (tile == 2)
            src = (const void*)&g_W_hi[C0 + r][koff];
        else
            src = (const void*)&g_W_lo[C0 + r][koff];
        cpasync16(dst, src);
    }
}

// ---- LSTM step: fp16-split HMMA GEMM, 64x64 tiles, fused gate epilogue ----
__global__ __launch_bounds__(128, 4) void lstm_step(int t) {
    extern __shared__ __align__(1024) char smem[];
    const uint32_t sb = s2u(smem);
    const int tid = threadIdx.x;
    const int wid = tid >> 5, lane = tid & 31;
    const int wm = wid & 1;       // 2 m-blocks of 32
    const int wn = wid >> 1;      // 2 n-blocks of 32
    const int row0 = blockIdx.x * TM;
    const int C0 = blockIdx.y * TN;
    const int buf = (t + 1) & 1;

    float d[2][4][4];
    #pragma unroll
    for (int a = 0; a < 2; a++)
        #pragma unroll
        for (int b = 0; b < 4; b++)
            #pragma unroll
            for (int c = 0; c < 4; c++) d[a][b][c] = 0.0f;

    produce(sb, 0, 0, t, row0, C0, tid);
    asm volatile("cp.async.commit_group;");

    // per-warp invariant pieces of the ldmatrix addresses
    const uint32_t b_lane = (wn * 32 + ((lane >> 4) & 1) * 8 + (lane & 7)) * ROWB
                          + ((lane >> 3) & 1) * 16 + 2 * TILE_BYTES;
    const uint32_t a_lane = (wm * 32 + (lane & 15)) * ROWB + (lane >> 4) * 16;

    for (int kc = 0; kc < NCH; kc++) {
        asm volatile("cp.async.wait_group 0;");
        __syncthreads();
        // issue next chunk AFTER barrier (stage (kc+1)&1 last read at kc-1)
        if (kc + 1 < NCH) {
            produce(sb, (kc + 1) & 1, kc + 1, t, row0, C0, tid);
            asm volatile("cp.async.commit_group;");
        }

        const uint32_t st = sb + (kc & 1) * STAGE_BYTES;
        #pragma unroll
        for (int k16 = 0; k16 < 2; k16++) {
            const uint32_t kb = k16 * 32;
            // ---- hoist all fragment loads (8 ldsm) before any MMA ----
            uint32_t bh[4][2], bl[4][2];
            #pragma unroll
            for (int g16 = 0; g16 < 2; g16++) {
                uint32_t ba = st + b_lane + g16 * (16 * ROWB) + kb;
                uint32_t r4[4];
                ldsm4(r4, ba);
                bh[g16 * 2 + 0][0] = r4[0]; bh[g16 * 2 + 0][1] = r4[1];
                bh[g16 * 2 + 1][0] = r4[2]; bh[g16 * 2 + 1][1] = r4[3];
                ldsm4(r4, ba + TILE_BYTES);
                bl[g16 * 2 + 0][0] = r4[0]; bl[g16 * 2 + 0][1] = r4[1];
                bl[g16 * 2 + 1][0] = r4[2]; bl[g16 * 2 + 1][1] = r4[3];
            }
            uint32_t ah[2][4], al[2][4];
            #pragma unroll
            for (int mf = 0; mf < 2; mf++) {
                uint32_t aa = st + a_lane + mf * (16 * ROWB) + kb;
                ldsm4(ah[mf], aa);
                ldsm4(al[mf], aa + TILE_BYTES);
            }
            // ---- 24 MMAs, term-major for RAW spacing ----
            #pragma unroll
            for (int mf = 0; mf < 2; mf++)
                #pragma unroll
                for (int nf = 0; nf < 4; nf++)
                    mma16816(d[mf][nf], ah[mf], bh[nf][0], bh[nf][1]);
            #pragma unroll
            for (int mf = 0; mf < 2; mf++)
                #pragma unroll
                for (int nf = 0; nf < 4; nf++)
                    mma16816(d[mf][nf], ah[mf], bl[nf][0], bl[nf][1]);
            #pragma unroll
            for (int mf = 0; mf < 2; mf++)
                #pragma unroll
                for (int nf = 0; nf < 4; nf++)
                    mma16816(d[mf][nf], al[mf], bh[nf][0], bh[nf][1]);
        }
    }

    // ---- fused LSTM epilogue ----
    // D frag: c0=[g][2tig], c1=[g][2tig+1], c2=[g+8][2tig], c3=[g+8][2tig+1]
    // cols gate-interleaved (C=4j+gate): tig even holds (i,f), odd holds (g,o)
    // of unit j = nf*2 + (tig>>1); shfl_xor(1) exchanges the complementary pair.
    const int g = lane >> 2, tig = lane & 3;
    #pragma unroll
    for (int nf = 0; nf < 4; nf++) {
        int j = (C0 >> 2) + wn * 8 + nf * 2 + (tig >> 1);
        float bi = g_bias[4 * j + 0], bf = g_bias[4 * j + 1];
        float bg = g_bias[4 * j + 2], bo = g_bias[4 * j + 3];
        #pragma unroll
        for (int mf = 0; mf < 2; mf++) {
            float c0 = d[mf][nf][0], c1 = d[mf][nf][1];
            float c2 = d[mf][nf][2], c3 = d[mf][nf][3];
            float s0 = __shfl_xor_sync(0xFFFFFFFFu, c0, 1);
            float s1 = __shfl_xor_sync(0xFFFFFFFFu, c1, 1);
            float s2 = __shfl_xor_sync(0xFFFFFFFFu, c2, 1);
            float s3 = __shfl_xor_sync(0xFFFFFFFFu, c3, 1);
            int row;
            float gi, gf, gg, go;
            if (!(tig & 1)) {
                row = row0 + wm * 32 + mf * 16 + g;
                gi = c0; gf = c1; gg = s0; go = s1;
            } else {
                row = row0 + wm * 32 + mf * 16 + g + 8;
                gi = s2; gf = s3; gg = c2; go = c3;
            }
            gi = fsig(gi + bi); gf = fsig(gf + bf);
            gg = ftanh_(gg + bg); go = fsig(go + bo);
            size_t ci = (size_t)j * BB + row;
            float cn = gf * g_c[ci] + gi * gg;
            g_c[ci] = cn;
            float h = go * ftanh_(cn);
            __half hh = __float2half(h);
            g_h_hi[buf][row][j] = hh;
            g_h_lo[buf][row][j] = __float2half(h - __half2float(hh));
        }
    }
}

// ---- final FC ----
__global__ void fc_kernel(const float* __restrict__ W_fc,
                          const float* __restrict__ b_fc,
                          float* __restrict__ out)
{
    __shared__ float hs[HH];
    int b = blockIdx.x;
    for (int k = threadIdx.x; k < HH; k += blockDim.x)
        hs[k] = __half2float(g_h_hi[0][b][k]) + __half2float(g_h_lo[0][b][k]);
    __syncthreads();
    int cls = threadIdx.x;
    if (cls < NC) {
        const float* w = &W_fc[(size_t)cls * HH];
        float acc = 0.0f;
        #pragma unroll 8
        for (int k = 0; k < HH; k++) acc += hs[k] * w[k];
        out[(size_t)b * NC + cls] = acc + b_fc[cls];
    }
}

extern "C" void kernel_launch(void* const* d_in, const int* in_sizes, int n_in,
                              void* d_out, int out_size)
{
    const float* msgs = (const float*)d_in[0];
    const float* W_ih = (const float*)d_in[1];
    const float* W_hh = (const float*)d_in[2];
    const float* b_ih = (const float*)d_in[3];
    const float* b_hh = (const float*)d_in[4];
    const float* W_fc = (const float*)d_in[5];
    const float* b_fc = (const float*)d_in[6];
    float* out = (float*)d_out;

    cudaFuncSetAttribute(lstm_step, cudaFuncAttributeMaxDynamicSharedMemorySize, SMEM_TOTAL);

    prep_w<<<(2048 * KTOT + 255) / 256, 256>>>(W_ih, W_hh, b_ih, b_hh);
    prep_x<<<(TT * BB * 32 + 255) / 256, 256>>>(msgs);
    init_state<<<(BB * HH + 255) / 256, 256>>>();

    dim3 grid(BB / TM, 2048 / TN);   // 32 x 32 = 1024 CTAs
    for (int t = 0; t < TT; t++)
        lstm_step<<<grid, 128, SMEM_TOTAL>>>(t);

    fc_kernel<<<BB, 128>>>(W_fc, b_fc, out);
}

// round 12
// speedup vs baseline: 1.5382x; 1.5382x over previous
#include <cuda_runtime.h>
#include <cuda_fp16.h>
#include <math.h>
#include <stdint.h>

// ---- dims ----
#define BB 2048
#define TT 128
#define VV 25
#define HH 512
#define NC 100
#define KTOT 544          // 512 (h) + 32 (x padded from 25)
#define TM 64
#define TN 64
#define NCH 17            // 544/32

// smem: rows of 32 halves padded to 80B (conflict-free ldmatrix)
#define ROWB 80
#define TILE_BYTES (64 * ROWB)          // 5120
#define STAGE_BYTES (4 * TILE_BYTES)    // Ahi, Alo, Bhi, Blo = 20480
#define SMEM_TOTAL (2 * STAGE_BYTES)    // 40960

// ---- persistent device state ----
__device__ __align__(1024) __half g_W_hi[2048][KTOT];   // permuted: row C=4j+gate, cols k
__device__ __align__(1024) __half g_W_lo[2048][KTOT];
__device__ __align__(1024) __half g_x_hi[TT][BB][32];
__device__ __align__(1024) __half g_x_lo[TT][BB][32];
__device__ __align__(1024) __half g_h_hi[2][BB][HH];
__device__ __align__(1024) __half g_h_lo[2][BB][HH];
__device__ __align__(1024) float  g_c[(size_t)HH * BB]; // [j][row]
__device__ float g_bias[2048];

// ---- helpers ----
__device__ __forceinline__ uint32_t s2u(const void* p) {
    uint32_t a;
    asm("{ .reg .u64 t; cvta.to.shared.u64 t, %1; cvt.u32.u64 %0, t; }" : "=r"(a) : "l"(p));
    return a;
}
__device__ __forceinline__ void ldsm4(uint32_t (&r)[4], uint32_t addr) {
    asm volatile("ldmatrix.sync.aligned.m8n8.x4.shared.b16 {%0,%1,%2,%3}, [%4];"
        : "=r"(r[0]), "=r"(r[1]), "=r"(r[2]), "=r"(r[3]) : "r"(addr));
}
__device__ __forceinline__ void mma16816(float (&d)[4], const uint32_t (&a)[4],
                                         uint32_t b0, uint32_t b1) {
    asm volatile("mma.sync.aligned.m16n8k16.row.col.f32.f16.f16.f32 "
        "{%0,%1,%2,%3}, {%4,%5,%6,%7}, {%8,%9}, {%0,%1,%2,%3};"
        : "+f"(d[0]), "+f"(d[1]), "+f"(d[2]), "+f"(d[3])
        : "r"(a[0]), "r"(a[1]), "r"(a[2]), "r"(a[3]), "r"(b0), "r"(b1));
}
__device__ __forceinline__ void cpasync16(uint32_t dst, const void* src) {
    size_t g = __cvta_generic_to_global(src);
    asm volatile("cp.async.cg.shared.global [%0], [%1], 16;" :: "r"(dst), "l"(g));
}
__device__ __forceinline__ float fsig(float x) { return 1.0f / (1.0f + __expf(-x)); }
__device__ __forceinline__ float ftanh_(float x) {
    float e = __expf(2.0f * x);
    return 1.0f - 2.0f / (e + 1.0f);
}

// ---- prep kernels ----
__global__ void prep_w(const float* __restrict__ W_ih, const float* __restrict__ W_hh,
                       const float* __restrict__ b_ih, const float* __restrict__ b_hh) {
    int idx = blockIdx.x * blockDim.x + threadIdx.x;
    if (idx >= 2048 * KTOT) return;
    int C = idx / KTOT, k = idx - C * KTOT;
    int orig = (C & 3) * HH + (C >> 2);     // gate-major -> interleaved
    float v = 0.0f;
    if (k < HH) v = W_hh[(size_t)orig * HH + k];
    else if (k - HH < VV) v = W_ih[(size_t)orig * VV + (k - HH)];
    __half hi = __float2half(v);
    g_W_hi[C][k] = hi;
    g_W_lo[C][k] = __float2half(v - __half2float(hi));
    if (k == 0) g_bias[C] = b_ih[orig] + b_hh[orig];
}
__global__ void prep_x(const float* __restrict__ msgs) {
    int idx = blockIdx.x * blockDim.x + threadIdx.x;
    if (idx >= TT * BB * 32) return;
    int kk = idx & 31, rt = idx >> 5;
    int row = rt & (BB - 1), t = rt >> 11;
    float v = (kk < VV) ? msgs[((size_t)row * TT + t) * VV + kk] : 0.0f;
    __half hi = __float2half(v);
    g_x_hi[t][row][kk] = hi;
    g_x_lo[t][row][kk] = __float2half(v - __half2float(hi));
}
__global__ void init_state() {
    size_t i = (size_t)blockIdx.x * blockDim.x + threadIdx.x;
    if (i < (size_t)BB * HH) {
        g_h_hi[0][0][i] = __float2half(0.0f);
        g_h_lo[0][0][i] = __float2half(0.0f);
        g_c[i] = 0.0f;
    }
}

// ---- per-chunk producer: 4 tiles x 64 rows x 4x16B chunks / 128 thr = 8 iters ----
__device__ __forceinline__ void produce(uint32_t sb, int stage, int kc, int t,
                                        int row0, int C0, int tid) {
    const int hb = t & 1;
    #pragma unroll
    for (int i = 0; i < 8; i++) {
        int p = tid + i * 128;
        int tile = p >> 8;            // 0..3
        int r = (p >> 2) & 63;
        int cc = p & 3;
        int koff = kc * 32 + cc * 8;  // halves
        uint32_t dst = sb + stage * STAGE_BYTES + tile * TILE_BYTES + r * ROWB + cc * 16;
        const void* src;
        if (tile == 0)
            src = (kc < 16) ? (const void*)&g_h_hi[hb][row0 + r][koff]
                            : (const void*)&g_x_hi[t][row0 + r][koff - 512];
        else if (tile == 1)
            src = (kc < 16) ? (const void*)&g_h_lo[hb][row0 + r][koff]
                            : (const void*)&g_x_lo[t][row0 + r][koff - 512];
        else if (tile == 2)
            src = (const void*)&g_W_hi[C0 + r][koff];
        else
            src = (const void*)&g_W_lo[C0 + r][koff];
        cpasync16(dst, src);
    }
}

// ---- LSTM step: fp16-split HMMA GEMM, 64x64 tiles, fused gate epilogue ----
__global__ __launch_bounds__(128, 4) void lstm_step(int t) {
    extern __shared__ __align__(1024) char smem[];
    const uint32_t sb = s2u(smem);
    const int tid = threadIdx.x;
    const int wid = tid >> 5, lane = tid & 31;
    const int wm = wid & 1;       // 2 m-blocks of 32
    const int wn = wid >> 1;      // 2 n-blocks of 32
    const int row0 = blockIdx.x * TM;
    const int C0 = blockIdx.y * TN;
    const int buf = (t + 1) & 1;

    float d[2][4][4];
    #pragma unroll
    for (int a = 0; a < 2; a++)
        #pragma unroll
        for (int b = 0; b < 4; b++)
            #pragma unroll
            for (int c = 0; c < 4; c++) d[a][b][c] = 0.0f;

    produce(sb, 0, 0, t, row0, C0, tid);
    asm volatile("cp.async.commit_group;");

    // per-warp invariant pieces of the ldmatrix addresses
    const uint32_t b_lane = (wn * 32 + ((lane >> 4) & 1) * 8 + (lane & 7)) * ROWB
                          + ((lane >> 3) & 1) * 16 + 2 * TILE_BYTES;
    const uint32_t a_lane = (wm * 32 + (lane & 15)) * ROWB + (lane >> 4) * 16;

    for (int kc = 0; kc < NCH; kc++) {
        asm volatile("cp.async.wait_group 0;");
        __syncthreads();
        // issue next chunk AFTER barrier (stage (kc+1)&1 last read at kc-1)
        if (kc + 1 < NCH) {
            produce(sb, (kc + 1) & 1, kc + 1, t, row0, C0, tid);
            asm volatile("cp.async.commit_group;");
        }

        const uint32_t st = sb + (kc & 1) * STAGE_BYTES;
        #pragma unroll
        for (int k16 = 0; k16 < 2; k16++) {
            const uint32_t kb = k16 * 32;
            // ---- hoist all fragment loads (8 ldsm) before any MMA ----
            uint32_t bh[4][2], bl[4][2];
            #pragma unroll
            for (int g16 = 0; g16 < 2; g16++) {
                uint32_t ba = st + b_lane + g16 * (16 * ROWB) + kb;
                uint32_t r4[4];
                ldsm4(r4, ba);
                bh[g16 * 2 + 0][0] = r4[0]; bh[g16 * 2 + 0][1] = r4[1];
                bh[g16 * 2 + 1][0] = r4[2]; bh[g16 * 2 + 1][1] = r4[3];
                ldsm4(r4, ba + TILE_BYTES);
                bl[g16 * 2 + 0][0] = r4[0]; bl[g16 * 2 + 0][1] = r4[1];
                bl[g16 * 2 + 1][0] = r4[2]; bl[g16 * 2 + 1][1] = r4[3];
            }
            uint32_t ah[2][4], al[2][4];
            #pragma unroll
            for (int mf = 0; mf < 2; mf++) {
                uint32_t aa = st + a_lane + mf * (16 * ROWB) + kb;
                ldsm4(ah[mf], aa);
                ldsm4(al[mf], aa + TILE_BYTES);
            }
            // ---- 24 MMAs, term-major for RAW spacing ----
            #pragma unroll
            for (int mf = 0; mf < 2; mf++)
                #pragma unroll
                for (int nf = 0; nf < 4; nf++)
                    mma16816(d[mf][nf], ah[mf], bh[nf][0], bh[nf][1]);
            #pragma unroll
            for (int mf = 0; mf < 2; mf++)
                #pragma unroll
                for (int nf = 0; nf < 4; nf++)
                    mma16816(d[mf][nf], ah[mf], bl[nf][0], bl[nf][1]);
            #pragma unroll
            for (int mf = 0; mf < 2; mf++)
                #pragma unroll
                for (int nf = 0; nf < 4; nf++)
                    mma16816(d[mf][nf], al[mf], bh[nf][0], bh[nf][1]);
        }
    }

    // ---- fused LSTM epilogue ----
    // D frag: c0=[g][2tig], c1=[g][2tig+1], c2=[g+8][2tig], c3=[g+8][2tig+1]
    // cols gate-interleaved (C=4j+gate): tig even holds (i,f), odd holds (g,o)
    // of unit j = nf*2 + (tig>>1); shfl_xor(1) exchanges the complementary pair.
    const int g = lane >> 2, tig = lane & 3;
    #pragma unroll
    for (int nf = 0; nf < 4; nf++) {
        int j = (C0 >> 2) + wn * 8 + nf * 2 + (tig >> 1);
        float bi = g_bias[4 * j + 0], bf = g_bias[4 * j + 1];
        float bg = g_bias[4 * j + 2], bo = g_bias[4 * j + 3];
        #pragma unroll
        for (int mf = 0; mf < 2; mf++) {
            float c0 = d[mf][nf][0], c1 = d[mf][nf][1];
            float c2 = d[mf][nf][2], c3 = d[mf][nf][3];
            float s0 = __shfl_xor_sync(0xFFFFFFFFu, c0, 1);
            float s1 = __shfl_xor_sync(0xFFFFFFFFu, c1, 1);
            float s2 = __shfl_xor_sync(0xFFFFFFFFu, c2, 1);
            float s3 = __shfl_xor_sync(0xFFFFFFFFu, c3, 1);
            int row;
            float gi, gf, gg, go;
            if (!(tig & 1)) {
                row = row0 + wm * 32 + mf * 16 + g;
                gi = c0; gf = c1; gg = s0; go = s1;
            } else {
                row = row0 + wm * 32 + mf * 16 + g + 8;
                gi = s2; gf = s3; gg = c2; go = c3;
            }
            gi = fsig(gi + bi); gf = fsig(gf + bf);
            gg = ftanh_(gg + bg); go = fsig(go + bo);
            size_t ci = (size_t)j * BB + row;
            float cn = gf * g_c[ci] + gi * gg;
            g_c[ci] = cn;
            float h = go * ftanh_(cn);
            __half hh = __float2half(h);
            g_h_hi[buf][row][j] = hh;
            g_h_lo[buf][row][j] = __float2half(h - __half2float(hh));
        }
    }
}

// ---- final FC ----
__global__ void fc_kernel(const float* __restrict__ W_fc,
                          const float* __restrict__ b_fc,
                          float* __restrict__ out)
{
    __shared__ float hs[HH];
    int b = blockIdx.x;
    for (int k = threadIdx.x; k < HH; k += blockDim.x)
        hs[k] = __half2float(g_h_hi[0][b][k]) + __half2float(g_h_lo[0][b][k]);
    __syncthreads();
    int cls = threadIdx.x;
    if (cls < NC) {
        const float* w = &W_fc[(size_t)cls * HH];
        float acc = 0.0f;
        #pragma unroll 8
        for (int k = 0; k < HH; k++) acc += hs[k] * w[k];
        out[(size_t)b * NC + cls] = acc + b_fc[cls];
    }
}

extern "C" void kernel_launch(void* const* d_in, const int* in_sizes, int n_in,
                              void* d_out, int out_size)
{
    const float* msgs = (const float*)d_in[0];
    const float* W_ih = (const float*)d_in[1];
    const float* W_hh = (const float*)d_in[2];
    const float* b_ih = (const float*)d_in[3];
    const float* b_hh = (const float*)d_in[4];
    const float* W_fc = (const float*)d_in[5];
    const float* b_fc = (const float*)d_in[6];
    float* out = (float*)d_out;

    cudaFuncSetAttribute(lstm_step, cudaFuncAttributeMaxDynamicSharedMemorySize, SMEM_TOTAL);

    prep_w<<<(2048 * KTOT + 255) / 256, 256>>>(W_ih, W_hh, b_ih, b_hh);
    prep_x<<<(TT * BB * 32 + 255) / 256, 256>>>(msgs);
    init_state<<<(BB * HH + 255) / 256, 256>>>();

    dim3 grid(BB / TM, 2048 / TN);   // 32 x 32 = 1024 CTAs
    for (int t = 0; t < TT; t++)
        lstm_step<<<grid, 128, SMEM_TOTAL>>>(t);

    fc_kernel<<<BB, 128>>>(W_fc, b_fc, out);
}